// round 14
// baseline (speedup 1.0000x reference)
#include <cuda_runtime.h>
#include <cuda_bf16.h>

// Problem shape (fixed by the dataset):
//   x : [16, 512, 64, 64] f32
//   s : [16, 512, 1, 4096] f32
//   z : [16, 1, 512, 1]   f32
//   wq: [1,1,5], wk: [1,1,5], wv: [512,1,3,3]
// Output: out [16,512,64,64], s_new [16,512,1,4096], z_new [16,1,512,1]

#define B 16
#define C 512
#define HW 4096
#define BC (B * C)            // 8192
#define OUT_ELEMS (BC * HW)   // 33554432

__device__ float g_y[BC];
__device__ unsigned g_flag[BC];

__device__ __forceinline__ void st_release_gpu(unsigned* p, unsigned v) {
    asm volatile("st.release.gpu.u32 [%0], %1;" :: "l"(p), "r"(v) : "memory");
}
__device__ __forceinline__ unsigned ld_acquire_gpu(const unsigned* p) {
    unsigned v;
    asm volatile("ld.acquire.gpu.u32 %0, [%1];" : "=r"(v) : "l"(p) : "memory");
    return v;
}

// ---------------------------------------------------------------------------
// Reset kernel: zero per-plane ready flags (required for every graph replay).
// ---------------------------------------------------------------------------
__global__ void __launch_bounds__(256) reset_kernel() {
    int i = blockIdx.x * 256 + threadIdx.x;
    if (i < BC) g_flag[i] = 0u;
}

// ---------------------------------------------------------------------------
// Fused single-pass kernel with HIDDEN neighbor wait. x read EXACTLY ONCE.
//  1. load x only (4 LDG.128; low MLP_p1 -> low block spread), scatter, sum
//  2. reduce; t0 publishes g_y[bc] + release flag  (NO wait here)
//  3. ALL threads compute conv accumulators acc[16] from the tile
//     -> this work is the absorb window for neighbor publish spread
//  4. t0 acquire-spins on <=4 same-batch neighbor flags (long since set),
//     computes Qf/Kf/coef/z_new
//  5. epilogue: per-chunk s load (streaming) + combine + 2 streaming stores
// ---------------------------------------------------------------------------
#define TP 68   // tile pitch: 66 rows x 68 floats; (r*68 + col0) % 4 == 0

__global__ void __launch_bounds__(256)
fused_kernel(const float* __restrict__ x,
             const float* __restrict__ s,
             const float* __restrict__ z,
             const float* __restrict__ wq,
             const float* __restrict__ wk,
             const float* __restrict__ wv,
             float* __restrict__ out,
             float* __restrict__ s_new,
             float* __restrict__ z_new) {
    int bc = blockIdx.x;
    int b = bc >> 9;
    int c = bc & 511;
    size_t base = (size_t)bc * HW;
    int t = threadIdx.x;

    __shared__ float tile[66 * TP];
    __shared__ float ws[8];
    __shared__ float sKf, sCf;

    // Phase 1: x loads only (keep front-batched MLP small).
    const float4* xp = reinterpret_cast<const float4*>(x + base);
    float4 xa[4];
#pragma unroll
    for (int k = 0; k < 4; k++) xa[k] = __ldcs(xp + t + k * 256);

    // Zero the halo ring while loads are in flight.
    if (t < 66) { tile[t] = 0.0f; tile[65 * TP + t] = 0.0f; }
    if (t < 64) { tile[(t + 1) * TP] = 0.0f; tile[(t + 1) * TP + 65] = 0.0f; }

    // Per-channel conv weights.
    float w[9];
#pragma unroll
    for (int j = 0; j < 9; j++) w[j] = __ldg(wv + c * 9 + j);

    // Scatter x into the haloed tile AND accumulate the plane sum.
    float sum = 0.0f;
#pragma unroll
    for (int k = 0; k < 4; k++) {
        int q = t + k * 256;          // float4 index 0..1023
        int p = q << 2;               // pixel
        int r = p >> 6;               // row 0..63
        int col = p & 63;             // col (multiple of 4)
        float* dst = &tile[(r + 1) * TP + col + 1];
        dst[0] = xa[k].x; dst[1] = xa[k].y; dst[2] = xa[k].z; dst[3] = xa[k].w;
        sum += (xa[k].x + xa[k].y) + (xa[k].z + xa[k].w);
    }

    // Block reduction of the plane sum.
#pragma unroll
    for (int o = 16; o > 0; o >>= 1) sum += __shfl_xor_sync(0xffffffffu, sum, o);
    if ((t & 31) == 0) ws[t >> 5] = sum;
    __syncthreads();   // covers tile scatter + ws

    // Publish the mean EARLY; no waiting yet.
    float mean = 0.0f;
    if (t == 0) {
        float s2 = ws[0];
#pragma unroll
        for (int j = 1; j < 8; j++) s2 += ws[j];
        mean = s2 * (1.0f / (float)HW);
        g_y[bc] = mean;
        st_release_gpu(&g_flag[bc], 1u);   // release orders g_y before flag
    }

    // Phase 2 (absorb window): conv accumulators from the tile, all threads.
    float acc[16];
#pragma unroll
    for (int k = 0; k < 4; k++) {
        int q = t + k * 256;
        int p = q << 2;
        int r = p >> 6;
        int col0 = p & 63;
        float a0 = 0.0f, a1 = 0.0f, a2 = 0.0f, a3 = 0.0f;
#pragma unroll
        for (int di = 0; di < 3; di++) {
            const float* rowp = &tile[(r + di) * TP + col0];
            float4 f4 = *reinterpret_cast<const float4*>(rowp);
            float2 f2 = *reinterpret_cast<const float2*>(rowp + 4);
            float w0 = w[di * 3 + 0], w1 = w[di * 3 + 1], w2 = w[di * 3 + 2];
            a0 = fmaf(w0, f4.x, fmaf(w1, f4.y, fmaf(w2, f4.z, a0)));
            a1 = fmaf(w0, f4.y, fmaf(w1, f4.z, fmaf(w2, f4.w, a1)));
            a2 = fmaf(w0, f4.z, fmaf(w1, f4.w, fmaf(w2, f2.x, a2)));
            a3 = fmaf(w0, f4.w, fmaf(w1, f2.x, fmaf(w2, f2.y, a3)));
        }
        acc[k * 4 + 0] = a0;
        acc[k * 4 + 1] = a1;
        acc[k * 4 + 2] = a2;
        acc[k * 4 + 3] = a3;
    }

    // Phase 3: t0 waits (neighbors published ~a conv-phase ago) + coefficients.
    if (t == 0) {
#pragma unroll
        for (int j = 0; j < 5; j++) {
            if (j == 2) continue;              // own plane
            int cc = c + j - 2;
            if ((unsigned)cc < (unsigned)C) {
                const unsigned* fl = &g_flag[(b << 9) + cc];
                while (ld_acquire_gpu(fl) == 0u) __nanosleep(20);
            }
        }
        float q = 0.0f, k = 0.0f;
#pragma unroll
        for (int j = 0; j < 5; j++) {
            int cc = c + j - 2;
            float v = 0.0f;
            if ((unsigned)cc < (unsigned)C)
                v = (cc == c) ? mean : g_y[(b << 9) + cc];
            q += __ldg(wq + j) * v;
            k += __ldg(wk + j) * v;
        }
        float Qf = (q > 0.0f) ? (q + 1.0f) : expf(q);
        float Kf = (k > 0.0f) ? (k + 1.0f) : expf(k);
        float zn = z[bc] + Kf;
        float qz = 1.0f / (Qf * (zn + 1e-6f));
        sKf = Kf;
        sCf = Qf * qz;
        z_new[bc] = zn;
    }
    __syncthreads();

    float Kf = sKf;
    float Cf = sCf;

    const float4* sp = reinterpret_cast<const float4*>(s + base);
    float4* op = reinterpret_cast<float4*>(out + base);
    float4* np = reinterpret_cast<float4*>(s_new + base);

    // Phase 4: stream s, combine with accumulators, stream out both results.
#pragma unroll
    for (int k = 0; k < 4; k++) {
        int q = t + k * 256;
        float4 sv = __ldcs(sp + q);
        float4 sn, ov;
        sn.x = sv.x + Kf * acc[k * 4 + 0];
        sn.y = sv.y + Kf * acc[k * 4 + 1];
        sn.z = sv.z + Kf * acc[k * 4 + 2];
        sn.w = sv.w + Kf * acc[k * 4 + 3];
        ov.x = Cf * sn.x;
        ov.y = Cf * sn.y;
        ov.z = Cf * sn.z;
        ov.w = Cf * sn.w;
        __stcs(np + q, sn);
        __stcs(op + q, ov);
    }
}

// ---------------------------------------------------------------------------
extern "C" void kernel_launch(void* const* d_in, const int* in_sizes, int n_in,
                              void* d_out, int out_size) {
    const float* x  = (const float*)d_in[0];
    const float* s  = (const float*)d_in[1];
    const float* z  = (const float*)d_in[2];
    const float* wq = (const float*)d_in[3];
    const float* wk = (const float*)d_in[4];
    const float* wv = (const float*)d_in[5];

    float* out   = (float*)d_out;                 // [BC, HW]
    float* s_new = out + (size_t)OUT_ELEMS;       // [BC, HW]
    float* z_new = s_new + (size_t)OUT_ELEMS;     // [BC]

    reset_kernel<<<BC / 256, 256>>>();
    fused_kernel<<<BC, 256>>>(x, s, z, wq, wk, wv, out, s_new, z_new);
}